// round 2
// baseline (speedup 1.0000x reference)
#include <cuda_runtime.h>
#include <cuda_bf16.h>
#include <cstdint>

// ---------------- problem constants ----------------
#define NMAX    8192
#define DDIM    128
#define TILE_M  128
#define TILE_N  128                   // columns per chunk
#define CSPLIT  2                     // column splits (grid = 64*2 = 128 CTAs)
#define CC      14.426950408889634f   // log2(e) / TEMPERATURE(=0.1)
#define LN2F    0.69314718055994531f
#define SKIP_T  25.0f                 // drop terms < 2^-25 of running max

#define TILE_BYTES (TILE_M * DDIM * 2)          // 32 KB (bf16)
#define SMEM_TOTAL (3 * TILE_BYTES)             // A + B0 + B1 = 96 KB

__device__ __align__(16) __nv_bfloat16 g_tbf[NMAX * DDIM];  // t in bf16
__device__ float  g_sC[NMAX];            // s_i * CC
__device__ float  g_dlabE[NMAX];         // |s_i - u_i| * CC
__device__ float2 g_part[CSPLIT][NMAX];  // per-split (max, sum of exp2)

// ---------------- low-level helpers ----------------
__device__ __forceinline__ uint32_t smem_u32(const void* p) {
    uint32_t a;
    asm("{ .reg .u64 t; cvta.to.shared.u64 t, %1; cvt.u32.u64 %0, t; }" : "=r"(a) : "l"(p));
    return a;
}
__device__ __forceinline__ void cp_async16(uint32_t dst, const void* src) {
    asm volatile("cp.async.cg.shared.global [%0], [%1], 16;" :: "r"(dst), "l"(src) : "memory");
}
#define CP_COMMIT() asm volatile("cp.async.commit_group;" ::: "memory")
#define CP_WAIT0()  asm volatile("cp.async.wait_group 0;" ::: "memory")

#define LDSM_X4(r, addr)                                                      \
    asm volatile("ldmatrix.sync.aligned.m8n8.x4.shared.b16 {%0,%1,%2,%3}, [%4];" \
        : "=r"((r)[0]), "=r"((r)[1]), "=r"((r)[2]), "=r"((r)[3]) : "r"(addr))

__device__ __forceinline__ void mma16816(float* c, const uint32_t* a,
                                         uint32_t b0, uint32_t b1) {
    asm volatile(
        "mma.sync.aligned.m16n8k16.row.col.f32.bf16.bf16.f32 "
        "{%0,%1,%2,%3}, {%4,%5,%6,%7}, {%8,%9}, {%0,%1,%2,%3};"
        : "+f"(c[0]), "+f"(c[1]), "+f"(c[2]), "+f"(c[3])
        : "r"(a[0]), "r"(a[1]), "r"(a[2]), "r"(a[3]), "r"(b0), "r"(b1));
}

// swizzled smem byte offset for (row, 16B-chunk) in a 128x128 bf16 tile
__device__ __forceinline__ uint32_t swz(int r, int c) {
    return (uint32_t)(r * 256 + ((c ^ (r & 7)) << 4));
}

// ---------------- K0: t fp32 -> bf16 global buffer ----------------
__global__ void k0_convert(const float* __restrict__ t) {
    int idx = blockIdx.x * blockDim.x + threadIdx.x;   // over total/4
    float4 v = reinterpret_cast<const float4*>(t)[idx];
    __nv_bfloat162 p0, p1;
    p0.x = __float2bfloat16(v.x); p0.y = __float2bfloat16(v.y);
    p1.x = __float2bfloat16(v.z); p1.y = __float2bfloat16(v.w);
    uint2 pk;
    pk.x = *reinterpret_cast<uint32_t*>(&p0);
    pk.y = *reinterpret_cast<uint32_t*>(&p1);
    reinterpret_cast<uint2*>(g_tbf)[idx] = pk;
}

// ---------------- K1: per-row scalars (fp32 exact) ----------------
__global__ void k1_rowprep(const float* __restrict__ q, const float* __restrict__ t,
                           const int* __restrict__ label, const int* __restrict__ jidx,
                           int n) {
    int i = blockIdx.x * 8 + (threadIdx.x >> 5);
    if (i >= n) return;
    int lane = threadIdx.x & 31;
    int j = jidx[i];

    float4 a = reinterpret_cast<const float4*>(q + (size_t)i * DDIM)[lane];
    float4 b = reinterpret_cast<const float4*>(q + (size_t)j * DDIM)[lane];
    float s = a.x * b.x + a.y * b.y + a.z * b.z + a.w * b.w;
    #pragma unroll
    for (int o = 16; o; o >>= 1) s += __shfl_xor_sync(0xFFFFFFFFu, s, o);

    int l = label[i];
    int col;
    if (l == i)       col = j;
    else if (j > i)   col = (l > i && l <= j) ? l - 1 : l;
    else              col = (l >= j && l < i) ? l + 1 : l;

    float4 c = reinterpret_cast<const float4*>(t + (size_t)i   * DDIM)[lane];
    float4 d = reinterpret_cast<const float4*>(t + (size_t)col * DDIM)[lane];
    float u = c.x * d.x + c.y * d.y + c.z * d.z + c.w * d.w;
    #pragma unroll
    for (int o = 16; o; o >>= 1) u += __shfl_xor_sync(0xFFFFFFFFu, u, o);

    if (lane == 0) {
        g_sC[i]    = s * CC;
        g_dlabE[i] = fabsf(s - u) * CC;
    }
}

// ---------------- K2: t@t^T (mma.sync bf16) + fused online logsumexp ----------
__global__ void __launch_bounds__(256, 1) k2_gemm_lse(int n) {
    extern __shared__ char smem[];
    const int tid = threadIdx.x, wid = tid >> 5, lane = tid & 31;
    const int wr = wid & 3;          // warp row group (32 rows each)
    const int wc = wid >> 2;         // warp col group (64 cols each)
    const int g = lane >> 2, tig = lane & 3;

    const int rowtile = blockIdx.x >> 1, split = blockIdx.x & 1;
    const int row0 = rowtile * TILE_M;
    const int ncols = n / CSPLIT;
    const int col0 = split * ncols;
    const int nch = ncols / TILE_N;   // 32

    const uint32_t sA  = smem_u32(smem);
    const uint32_t sB0 = sA + TILE_BYTES;
    const uint32_t sB1 = sB0 + TILE_BYTES;

    // A tile + B chunk 0 via cp.async
    {
        const char* Ag = (const char*)(g_tbf + (size_t)row0 * DDIM);
        const char* Bg = (const char*)(g_tbf + (size_t)col0 * DDIM);
        for (int idx = tid; idx < 2048; idx += 256) {
            int r = idx >> 4, c = idx & 15;
            cp_async16(sA  + swz(r, c), Ag + idx * 16);
            cp_async16(sB0 + swz(r, c), Bg + idx * 16);
        }
        CP_COMMIT();
        CP_WAIT0();
        __syncthreads();
    }

    // per-thread rows: q = mf*2 + hi -> row = wr*32 + mf*16 + hi*8 + g
    float sCv[4], mmax[4], rsum[4];
    #pragma unroll
    for (int qq = 0; qq < 4; qq++) {
        int row = row0 + wr * 32 + (qq >> 1) * 16 + (qq & 1) * 8 + g;
        sCv[qq] = g_sC[row];
        mmax[qq] = -1e30f;
        rsum[qq] = 0.f;
    }

    for (int it = 0; it < nch; ++it) {
        const uint32_t sBc = (it & 1) ? sB1 : sB0;
        // prefetch next B chunk (other buffer) — overlaps the mma loop
        if (it + 1 < nch) {
            const uint32_t sBn = (it & 1) ? sB0 : sB1;
            const char* src = (const char*)(g_tbf + (size_t)(col0 + (it + 1) * TILE_N) * DDIM);
            for (int idx = tid; idx < 2048; idx += 256) {
                int r = idx >> 4, c = idx & 15;
                cp_async16(sBn + swz(r, c), src + idx * 16);
            }
            CP_COMMIT();
        }

        // ---- 128x128x128 per CTA: warp does 32x64, frags 2(M) x 8(N) ----
        float acc[2][8][4];
        #pragma unroll
        for (int mf = 0; mf < 2; mf++)
            #pragma unroll
            for (int nf = 0; nf < 8; nf++)
                #pragma unroll
                for (int e = 0; e < 4; e++) acc[mf][nf][e] = 0.f;

        #pragma unroll
        for (int kc = 0; kc < 8; kc++) {        // K = 8 * 16
            uint32_t a0[4], a1[4];
            {
                int r = wr * 32 + (lane & 15);
                int c = kc * 2 + (lane >> 4);
                LDSM_X4(a0, sA + swz(r, c));
                LDSM_X4(a1, sA + swz(r + 16, c));
            }
            #pragma unroll
            for (int p = 0; p < 4; p++) {        // pairs of N frags
                uint32_t b[4];
                int r = wc * 64 + p * 16 + ((lane >> 4) << 3) + (lane & 7);
                int c = kc * 2 + ((lane >> 3) & 1);
                LDSM_X4(b, sBc + swz(r, c));
                mma16816(acc[0][2 * p],     a0, b[0], b[1]);
                mma16816(acc[0][2 * p + 1], a0, b[2], b[3]);
                mma16816(acc[1][2 * p],     a1, b[0], b[1]);
                mma16816(acc[1][2 * p + 1], a1, b[2], b[3]);
            }
        }

        // ---- fold chunk into per-row online logsumexp (base-2) ----
        #pragma unroll
        for (int mf = 0; mf < 2; mf++)
            #pragma unroll
            for (int nf = 0; nf < 8; nf++)
                #pragma unroll
                for (int e = 0; e < 4; e++) {
                    int qq = mf * 2 + (e >> 1);
                    float E = fabsf(fmaf(acc[mf][nf][e], -CC, sCv[qq]));
                    if (E > mmax[qq] - SKIP_T) {          // rare beyond early its
                        if (E > mmax[qq]) {
                            rsum[qq] = fmaf(rsum[qq], exp2f(mmax[qq] - E), 1.f);
                            mmax[qq] = E;
                        } else {
                            rsum[qq] += exp2f(E - mmax[qq]);
                        }
                    }
                }

        CP_WAIT0();
        __syncthreads();
    }

    // ---- reduce across the 4 lanes sharing each row ----
    #pragma unroll
    for (int qq = 0; qq < 4; qq++) {
        #pragma unroll
        for (int off = 1; off < 4; off <<= 1) {
            float om = __shfl_xor_sync(0xFFFFFFFFu, mmax[qq], off);
            float orr = __shfl_xor_sync(0xFFFFFFFFu, rsum[qq], off);
            float M = fmaxf(mmax[qq], om);
            rsum[qq] = rsum[qq] * exp2f(mmax[qq] - M) + orr * exp2f(om - M);
            mmax[qq] = M;
        }
    }
    __syncthreads();                 // smem reuse barrier

    // ---- combine the two column-group warps, write per-row partials ----
    float2* cb = reinterpret_cast<float2*>(smem);
    if (wc == 1 && tig == 0) {
        #pragma unroll
        for (int qq = 0; qq < 4; qq++) {
            int rl = wr * 32 + (qq >> 1) * 16 + (qq & 1) * 8 + g;
            cb[rl] = make_float2(mmax[qq], rsum[qq]);
        }
    }
    __syncthreads();
    if (wc == 0 && tig == 0) {
        #pragma unroll
        for (int qq = 0; qq < 4; qq++) {
            int rl = wr * 32 + (qq >> 1) * 16 + (qq & 1) * 8 + g;
            float2 o = cb[rl];
            float M = fmaxf(mmax[qq], o.x);
            float R = rsum[qq] * exp2f(mmax[qq] - M) + o.y * exp2f(o.x - M);
            g_part[split][row0 + rl] = make_float2(M, R);
        }
    }
}

// ---------------- K3: deterministic combine + mean ----------------
__global__ void k3_final(float* __restrict__ out, int n) {
    __shared__ float red[256];
    int tid = threadIdx.x;
    float acc = 0.f;
    for (int i = tid; i < n; i += 256) {
        float2 a = g_part[0][i], b = g_part[1][i];
        float M = fmaxf(a.x, b.x);
        float R = a.y * exp2f(a.x - M) + b.y * exp2f(b.x - M);
        acc += (M + log2f(R)) - g_dlabE[i];   // base-2 units
    }
    red[tid] = acc;
    __syncthreads();
    #pragma unroll
    for (int s = 128; s > 0; s >>= 1) {
        if (tid < s) red[tid] += red[tid + s];
        __syncthreads();
    }
    if (tid == 0) out[0] = red[0] * (LN2F / (float)n);
}

// ---------------- launch ----------------
extern "C" void kernel_launch(void* const* d_in, const int* in_sizes, int n_in,
                              void* d_out, int out_size) {
    const float* q     = (const float*)d_in[0];
    const float* t     = (const float*)d_in[1];
    const int*   label = (const int*)d_in[2];
    const int*   jidx  = (const int*)d_in[3];
    int n = in_sizes[2];   // = N (8192)

    cudaFuncSetAttribute(k2_gemm_lse, cudaFuncAttributeMaxDynamicSharedMemorySize, SMEM_TOTAL);

    k0_convert<<<(n * DDIM / 4) / 256, 256>>>(t);
    k1_rowprep<<<n / 8, 256>>>(q, t, label, jidx, n);
    k2_gemm_lse<<<(n / TILE_M) * CSPLIT, 256, SMEM_TOTAL>>>(n);
    k3_final<<<1, 256>>>((float*)d_out, n);
}

// round 3
// speedup vs baseline: 1.9808x; 1.9808x over previous
#include <cuda_runtime.h>
#include <cuda_bf16.h>
#include <cstdint>

// ---------------- problem constants ----------------
#define NMAX    8192
#define DDIM    128
#define TM      128                   // tile size (M and N)
#define NTILES  (NMAX / TM)           // 64
#define CC      14.426950408889634f   // log2(e) / TEMPERATURE(=0.1)
#define LN2F    0.69314718055994531f
#define SKIP_T  25.0f                 // drop terms < 2^-25 of max

#define TILE_BYTES (TM * DDIM * 2)    // 32 KB bf16

// smem layout (bytes)
#define OFF_A     0
#define OFF_B     (TILE_BYTES)
#define OFF_SROW  (2 * TILE_BYTES)            // 128 f32
#define OFF_SCOL  (OFF_SROW + 512)            // 128 f32
#define OFF_ROWM  (OFF_SCOL + 512)            // 2 x 128 f32
#define OFF_ROWS  (OFF_ROWM + 1024)           // 2 x 128 f32
#define OFF_COLM  (OFF_ROWS + 1024)           // 4 x 128 f32
#define OFF_COLMF (OFF_COLM + 2048)           // 128 f32
#define OFF_COLS  (OFF_COLMF + 512)           // 4 x 128 f32
#define SMEM_K2   (OFF_COLS + 2048)           // ~73 KB

__device__ __align__(16) __nv_bfloat16 g_tbf[NMAX * DDIM];  // t in bf16
__device__ float  g_sC[NMAX];             // s_i * CC
__device__ float  g_dlabE[NMAX];          // |s_i - u_i| * CC
__device__ float2 g_c[NTILES * NMAX];     // [slot J][row] = (max, sum)
__device__ float  g_bpart[32];            // k3 partials

// ---------------- low-level helpers ----------------
__device__ __forceinline__ uint32_t smem_u32(const void* p) {
    uint32_t a;
    asm("{ .reg .u64 t; cvta.to.shared.u64 t, %1; cvt.u32.u64 %0, t; }" : "=r"(a) : "l"(p));
    return a;
}
__device__ __forceinline__ void cp_async16(uint32_t dst, const void* src) {
    asm volatile("cp.async.cg.shared.global [%0], [%1], 16;" :: "r"(dst), "l"(src) : "memory");
}
#define CP_COMMIT() asm volatile("cp.async.commit_group;" ::: "memory")
#define CP_WAIT0()  asm volatile("cp.async.wait_group 0;" ::: "memory")

#define LDSM_X4(r, addr)                                                      \
    asm volatile("ldmatrix.sync.aligned.m8n8.x4.shared.b16 {%0,%1,%2,%3}, [%4];" \
        : "=r"((r)[0]), "=r"((r)[1]), "=r"((r)[2]), "=r"((r)[3]) : "r"(addr))

__device__ __forceinline__ void mma16816(float* c, const uint32_t* a,
                                         uint32_t b0, uint32_t b1) {
    asm volatile(
        "mma.sync.aligned.m16n8k16.row.col.f32.bf16.bf16.f32 "
        "{%0,%1,%2,%3}, {%4,%5,%6,%7}, {%8,%9}, {%0,%1,%2,%3};"
        : "+f"(c[0]), "+f"(c[1]), "+f"(c[2]), "+f"(c[3])
        : "r"(a[0]), "r"(a[1]), "r"(a[2]), "r"(a[3]), "r"(b0), "r"(b1));
}

// swizzled smem byte offset for (row, 16B-chunk) in a 128x128 bf16 tile
__device__ __forceinline__ uint32_t swz(int r, int c) {
    return (uint32_t)(r * 256 + ((c ^ (r & 7)) << 4));
}

// ---------------- K0: t fp32 -> bf16 ----------------
__global__ void k0_convert(const float* __restrict__ t) {
    int idx = blockIdx.x * blockDim.x + threadIdx.x;
    float4 v = reinterpret_cast<const float4*>(t)[idx];
    __nv_bfloat162 p0, p1;
    p0.x = __float2bfloat16(v.x); p0.y = __float2bfloat16(v.y);
    p1.x = __float2bfloat16(v.z); p1.y = __float2bfloat16(v.w);
    uint2 pk;
    pk.x = *reinterpret_cast<uint32_t*>(&p0);
    pk.y = *reinterpret_cast<uint32_t*>(&p1);
    reinterpret_cast<uint2*>(g_tbf)[idx] = pk;
}

// ---------------- K1: per-row scalars (fp32 exact) ----------------
__global__ void k1_rowprep(const float* __restrict__ q, const float* __restrict__ t,
                           const int* __restrict__ label, const int* __restrict__ jidx,
                           int n) {
    int i = blockIdx.x * 8 + (threadIdx.x >> 5);
    if (i >= n) return;
    int lane = threadIdx.x & 31;
    int j = jidx[i];

    float4 a = reinterpret_cast<const float4*>(q + (size_t)i * DDIM)[lane];
    float4 b = reinterpret_cast<const float4*>(q + (size_t)j * DDIM)[lane];
    float s = a.x * b.x + a.y * b.y + a.z * b.z + a.w * b.w;
    #pragma unroll
    for (int o = 16; o; o >>= 1) s += __shfl_xor_sync(0xFFFFFFFFu, s, o);

    int l = label[i];
    int col;
    if (l == i)       col = j;
    else if (j > i)   col = (l > i && l <= j) ? l - 1 : l;
    else              col = (l >= j && l < i) ? l + 1 : l;

    float4 c = reinterpret_cast<const float4*>(t + (size_t)i   * DDIM)[lane];
    float4 d = reinterpret_cast<const float4*>(t + (size_t)col * DDIM)[lane];
    float u = c.x * d.x + c.y * d.y + c.z * d.z + c.w * d.w;
    #pragma unroll
    for (int o = 16; o; o >>= 1) u += __shfl_xor_sync(0xFFFFFFFFu, u, o);

    if (lane == 0) {
        g_sC[i]    = s * CC;
        g_dlabE[i] = fabsf(s - u) * CC;
    }
}

// ---------------- K2: symmetric t@t^T tiles + dual-direction LSE partials ----
__global__ void __launch_bounds__(256, 2) k2_sym(int ntiles) {
    extern __shared__ char smem[];
    const int tid = threadIdx.x, wid = tid >> 5, lane = tid & 31;
    const int wr = wid & 3;          // warp row group (32 rows)
    const int wc = wid >> 2;         // warp col group (64 cols)
    const int g = lane >> 2, tig = lane & 3;

    // decode blockIdx -> (I, J), I <= J
    int b = blockIdx.x;
    int I;
    {
        float nn = 2.0f * ntiles + 1.0f;
        I = (int)((nn - sqrtf(nn * nn - 8.0f * (float)b)) * 0.5f);
        if (I < 0) I = 0;
        while ((I + 1) * ntiles - ((I + 1) * I) / 2 <= b) ++I;
        while (I * ntiles - (I * (I - 1)) / 2 > b) --I;
    }
    const int J = I + (b - (I * ntiles - (I * (I - 1)) / 2));
    const bool diag = (I == J);
    const int row0 = I * TM, col0 = J * TM;

    const uint32_t sA = smem_u32(smem);
    const uint32_t sB = diag ? sA : (sA + OFF_B);
    float* sRowBuf = reinterpret_cast<float*>(smem + OFF_SROW);
    float* sColBuf = reinterpret_cast<float*>(smem + OFF_SCOL);
    float* rowMbuf = reinterpret_cast<float*>(smem + OFF_ROWM);
    float* rowSbuf = reinterpret_cast<float*>(smem + OFF_ROWS);
    float* colMbuf = reinterpret_cast<float*>(smem + OFF_COLM);
    float* colMF   = reinterpret_cast<float*>(smem + OFF_COLMF);
    float* colSbuf = reinterpret_cast<float*>(smem + OFF_COLS);

    // ---- stage tiles + s vectors ----
    {
        const char* Ag = (const char*)(g_tbf + (size_t)row0 * DDIM);
        for (int idx = tid; idx < 2048; idx += 256)
            cp_async16(sA + swz(idx >> 4, idx & 15), Ag + idx * 16);
        if (!diag) {
            const char* Bg = (const char*)(g_tbf + (size_t)col0 * DDIM);
            for (int idx = tid; idx < 2048; idx += 256)
                cp_async16(sA + OFF_B + swz(idx >> 4, idx & 15), Bg + idx * 16);
        }
        if (tid < 128) sRowBuf[tid] = g_sC[row0 + tid];
        else           sColBuf[tid - 128] = g_sC[col0 + tid - 128];
        CP_COMMIT();
        CP_WAIT0();
        __syncthreads();
    }

    // ---- 128x128x128 MMA: warp does 32x64 ----
    float acc[2][8][4];
    #pragma unroll
    for (int mf = 0; mf < 2; mf++)
        #pragma unroll
        for (int nf = 0; nf < 8; nf++)
            #pragma unroll
            for (int e = 0; e < 4; e++) acc[mf][nf][e] = 0.f;

    #pragma unroll
    for (int kc = 0; kc < 8; kc++) {
        uint32_t a0[4], a1[4];
        {
            int r = wr * 32 + (lane & 15);
            int c = kc * 2 + (lane >> 4);
            LDSM_X4(a0, sA + swz(r, c));
            LDSM_X4(a1, sA + swz(r + 16, c));
        }
        #pragma unroll
        for (int p = 0; p < 4; p++) {
            uint32_t bb[4];
            int r = wc * 64 + p * 16 + ((lane >> 4) << 3) + (lane & 7);
            int c = kc * 2 + ((lane >> 3) & 1);
            LDSM_X4(bb, sB + swz(r, c));
            mma16816(acc[0][2 * p],     a0, bb[0], bb[1]);
            mma16816(acc[0][2 * p + 1], a0, bb[2], bb[3]);
            mma16816(acc[1][2 * p],     a1, bb[0], bb[1]);
            mma16816(acc[1][2 * p + 1], a1, bb[2], bb[3]);
        }
    }

    // fragment coords: row_local = wr*32 + mf*16 + (e>>1)*8 + g
    //                  col_local = wc*64 + nf*8 + tig*2 + (e&1)

    // ======== ROW PASS (rows of tile I, s = sRow, slot J) ========
    float sRow[4], rM[4], Mrow[4], rS[4];
    #pragma unroll
    for (int qq = 0; qq < 4; qq++) {
        sRow[qq] = sRowBuf[wr * 32 + (qq >> 1) * 16 + (qq & 1) * 8 + g];
        rM[qq] = -1e30f;
    }
    #pragma unroll
    for (int mf = 0; mf < 2; mf++)
        #pragma unroll
        for (int nf = 0; nf < 8; nf++)
            #pragma unroll
            for (int e = 0; e < 4; e++) {
                int qq = mf * 2 + (e >> 1);
                float E = fabsf(fmaf(acc[mf][nf][e], -CC, sRow[qq]));
                rM[qq] = fmaxf(rM[qq], E);
            }
    #pragma unroll
    for (int qq = 0; qq < 4; qq++) {   // merge across tig (same row, 4 lanes)
        rM[qq] = fmaxf(rM[qq], __shfl_xor_sync(0xFFFFFFFFu, rM[qq], 1));
        rM[qq] = fmaxf(rM[qq], __shfl_xor_sync(0xFFFFFFFFu, rM[qq], 2));
    }
    if (tig == 0) {
        #pragma unroll
        for (int qq = 0; qq < 4; qq++)
            rowMbuf[wc * 128 + wr * 32 + (qq >> 1) * 16 + (qq & 1) * 8 + g] = rM[qq];
    }
    __syncthreads();
    #pragma unroll
    for (int qq = 0; qq < 4; qq++) {
        float other = rowMbuf[(1 - wc) * 128 + wr * 32 + (qq >> 1) * 16 + (qq & 1) * 8 + g];
        Mrow[qq] = fmaxf(rM[qq], other);
        rS[qq] = 0.f;
    }
    #pragma unroll
    for (int mf = 0; mf < 2; mf++)
        #pragma unroll
        for (int nf = 0; nf < 8; nf++)
            #pragma unroll
            for (int e = 0; e < 4; e++) {
                int qq = mf * 2 + (e >> 1);
                float E = fabsf(fmaf(acc[mf][nf][e], -CC, sRow[qq]));
                if (E > Mrow[qq] - SKIP_T) rS[qq] += exp2f(E - Mrow[qq]);
            }
    #pragma unroll
    for (int qq = 0; qq < 4; qq++) {
        rS[qq] += __shfl_xor_sync(0xFFFFFFFFu, rS[qq], 1);
        rS[qq] += __shfl_xor_sync(0xFFFFFFFFu, rS[qq], 2);
    }
    if (tig == 0) {
        #pragma unroll
        for (int qq = 0; qq < 4; qq++)
            rowSbuf[wc * 128 + wr * 32 + (qq >> 1) * 16 + (qq & 1) * 8 + g] = rS[qq];
    }
    __syncthreads();
    if (wc == 0 && tig == 0) {
        #pragma unroll
        for (int qq = 0; qq < 4; qq++) {
            int rl = wr * 32 + (qq >> 1) * 16 + (qq & 1) * 8 + g;
            float S = rS[qq] + rowSbuf[128 + rl];
            g_c[(size_t)J * NMAX + row0 + rl] = make_float2(Mrow[qq], S);
        }
    }

    // ======== COL PASS (rows of tile J, s = sCol, slot I) ========
    if (!diag) {
        float sColv[16], cM[16];
        #pragma unroll
        for (int nf = 0; nf < 8; nf++)
            #pragma unroll
            for (int p = 0; p < 2; p++) {
                sColv[nf * 2 + p] = sColBuf[wc * 64 + nf * 8 + tig * 2 + p];
                cM[nf * 2 + p] = -1e30f;
            }
        #pragma unroll
        for (int mf = 0; mf < 2; mf++)
            #pragma unroll
            for (int nf = 0; nf < 8; nf++)
                #pragma unroll
                for (int e = 0; e < 4; e++) {
                    int ii = nf * 2 + (e & 1);
                    float E = fabsf(fmaf(acc[mf][nf][e], -CC, sColv[ii]));
                    cM[ii] = fmaxf(cM[ii], E);
                }
        #pragma unroll
        for (int ii = 0; ii < 16; ii++) {   // merge across g (8 lanes share col)
            cM[ii] = fmaxf(cM[ii], __shfl_xor_sync(0xFFFFFFFFu, cM[ii], 4));
            cM[ii] = fmaxf(cM[ii], __shfl_xor_sync(0xFFFFFFFFu, cM[ii], 8));
            cM[ii] = fmaxf(cM[ii], __shfl_xor_sync(0xFFFFFFFFu, cM[ii], 16));
        }
        if (lane < 4) {   // g==0 lanes (tig = lane)
            #pragma unroll
            for (int ii = 0; ii < 16; ii++)
                colMbuf[wr * 128 + wc * 64 + (ii >> 1) * 8 + lane * 2 + (ii & 1)] = cM[ii];
        }
        __syncthreads();
        if (wr == 0) {    // wid 0 & 4 combine 4 warp-rows
            #pragma unroll
            for (int rep = 0; rep < 2; rep++) {
                int cl = wc * 64 + lane + rep * 32;
                float m = colMbuf[cl];
                m = fmaxf(m, colMbuf[128 + cl]);
                m = fmaxf(m, colMbuf[256 + cl]);
                m = fmaxf(m, colMbuf[384 + cl]);
                colMF[cl] = m;
            }
        }
        __syncthreads();
        float cS[16], McF[16];
        #pragma unroll
        for (int ii = 0; ii < 16; ii++) {
            McF[ii] = colMF[wc * 64 + (ii >> 1) * 8 + tig * 2 + (ii & 1)];
            cS[ii] = 0.f;
        }
        #pragma unroll
        for (int mf = 0; mf < 2; mf++)
            #pragma unroll
            for (int nf = 0; nf < 8; nf++)
                #pragma unroll
                for (int e = 0; e < 4; e++) {
                    int ii = nf * 2 + (e & 1);
                    float E = fabsf(fmaf(acc[mf][nf][e], -CC, sColv[ii]));
                    if (E > McF[ii] - SKIP_T) cS[ii] += exp2f(E - McF[ii]);
                }
        #pragma unroll
        for (int ii = 0; ii < 16; ii++) {
            cS[ii] += __shfl_xor_sync(0xFFFFFFFFu, cS[ii], 4);
            cS[ii] += __shfl_xor_sync(0xFFFFFFFFu, cS[ii], 8);
            cS[ii] += __shfl_xor_sync(0xFFFFFFFFu, cS[ii], 16);
        }
        if (lane < 4) {
            #pragma unroll
            for (int ii = 0; ii < 16; ii++)
                colSbuf[wr * 128 + wc * 64 + (ii >> 1) * 8 + lane * 2 + (ii & 1)] = cS[ii];
        }
        __syncthreads();
        if (wr == 0) {
            #pragma unroll
            for (int rep = 0; rep < 2; rep++) {
                int cl = wc * 64 + lane + rep * 32;
                float S = colSbuf[cl] + colSbuf[128 + cl] +
                          colSbuf[256 + cl] + colSbuf[384 + cl];
                g_c[(size_t)I * NMAX + col0 + cl] = make_float2(colMF[cl], S);
            }
        }
    }
}

// ---------------- K3: per-row combine of 64 partials + block sums ----------
__global__ void k3_rows(int n, int ntiles) {
    __shared__ float red[256];
    int row = blockIdx.x * 256 + threadIdx.x;
    // pass 1: global max across slots
    float M = -1e30f;
    for (int s = 0; s < ntiles; s++)
        M = fmaxf(M, g_c[(size_t)s * NMAX + row].x);
    // pass 2: sum relative to M
    float S = 0.f;
    for (int s = 0; s < ntiles; s++) {
        float2 v = g_c[(size_t)s * NMAX + row];
        if (v.x > M - SKIP_T - 8.f) S += v.y * exp2f(v.x - M);
    }
    float val = (M + log2f(S)) - g_dlabE[row];
    red[threadIdx.x] = val;
    __syncthreads();
    #pragma unroll
    for (int s = 128; s > 0; s >>= 1) {
        if (threadIdx.x < s) red[threadIdx.x] += red[threadIdx.x + s];
        __syncthreads();
    }
    if (threadIdx.x == 0) g_bpart[blockIdx.x] = red[0];
}

// ---------------- K4: final 32-value reduce ----------------
__global__ void k4_final(float* __restrict__ out, int n, int nblk) {
    int lane = threadIdx.x;
    float v = (lane < nblk) ? g_bpart[lane] : 0.f;
    #pragma unroll
    for (int o = 16; o; o >>= 1) v += __shfl_xor_sync(0xFFFFFFFFu, v, o);
    if (lane == 0) out[0] = v * (LN2F / (float)n);
}

// ---------------- launch ----------------
extern "C" void kernel_launch(void* const* d_in, const int* in_sizes, int n_in,
                              void* d_out, int out_size) {
    const float* q     = (const float*)d_in[0];
    const float* t     = (const float*)d_in[1];
    const int*   label = (const int*)d_in[2];
    const int*   jidx  = (const int*)d_in[3];
    int n = in_sizes[2];            // 8192
    int ntiles = n / TM;            // 64
    int pairs = ntiles * (ntiles + 1) / 2;   // 2080
    int nblk = n / 256;             // 32

    cudaFuncSetAttribute(k2_sym, cudaFuncAttributeMaxDynamicSharedMemorySize, SMEM_K2);

    k0_convert<<<(n * DDIM / 4) / 256, 256>>>(t);
    k1_rowprep<<<n / 8, 256>>>(q, t, label, jidx, n);
    k2_sym<<<pairs, 256, SMEM_K2>>>(ntiles);
    k3_rows<<<nblk, 256>>>(n, ntiles);
    k4_final<<<1, 32>>>((float*)d_out, n, nblk);
}